// round 5
// baseline (speedup 1.0000x reference)
#include <cuda_runtime.h>
#include <math.h>

// Problem constants
#define BATCH 8192
#define TT    128     // T
#define FF    63      // F
#define HH    128     // H
#define PP    64      // P (steps)
#define GG    512     // 4*H gates
#define II    64      // input width = 1 + F

#define MROWS    64                 // batch rows per block
#define NTHREADS 512
#define NBLOCKS  (BATCH / MROWS)    // 128

// One-time scratch: k-major combined weights Wt[k][g], k in [0,192):
//   k < 64   -> W_ih[g][k]   (k=0 is the recurrent-out column)
//   k >= 64  -> W_hh[g][k-64]
__device__ float g_Wt[192 * 512];
__device__ float g_bsum[512];

__global__ void setup_kernel(const float* __restrict__ Wih,
                             const float* __restrict__ Whh,
                             const float* __restrict__ bih,
                             const float* __restrict__ bhh) {
    int k = blockIdx.x;      // 0..191
    int g = threadIdx.x;     // 0..511
    float v = (k < II) ? Wih[g * II + k] : Whh[g * HH + (k - II)];
    g_Wt[k * GG + g] = v;
    if (k == 0) g_bsum[g] = bih[g] + bhh[g];
}

__device__ __forceinline__ float sigf(float v) {
    return 1.0f / (1.0f + expf(-v));
}

// Persistent LSTM: each block owns MROWS batch rows for all PP steps.
// Thread tile: 4 rows x 4 j-cols x 4 gate types (i,f,g,o) -> c stays in regs.
// Mapping: lane%16 -> row-group (rows vary across lanes -> coalesced/broadcast-
// free W LDG, swizzled LDS); warp*2 + lane/16 -> j-group (distinct W data per
// warp -> no redundant L1tex wavefronts).
__global__ __launch_bounds__(NTHREADS, 1)
void lstm_kernel(const float* __restrict__ x,
                 const float* __restrict__ z,
                 const float* __restrict__ h0,
                 const float* __restrict__ c0,
                 const float* __restrict__ Wout,
                 const float* __restrict__ bout,
                 float* __restrict__ Y) {
    // XOR-swizzled tiles: addr(row, col) = row*stride + (col ^ (row & 31))
    __shared__ float inp_s[MROWS * 64];    // 16 KB  (col 0 = recurrent out)
    __shared__ float h_s[MROWS * 128];     // 32 KB

    const int tid  = threadIdx.x;
    const int b0   = blockIdx.x * MROWS;
    const int w    = tid >> 5;
    const int lane = tid & 31;
    const int rg   = lane & 15;                 // 0..15
    const int jg   = (w << 1) | (lane >> 4);    // 0..31
    const int row0 = rg << 2;                   // 0..60
    const int j0   = jg << 2;                   // 0..124

    // ---- init h_s from h0 (swizzled) ----
    for (int idx = tid; idx < MROWS * HH; idx += NTHREADS) {
        int r = idx >> 7, k = idx & 127;
        h_s[r * 128 + (k ^ (r & 31))] = h0[(b0 + r) * HH + k];
    }
    // ---- init recurrent-out column from x[:, T-1, 0] ----
    for (int r = tid; r < MROWS; r += NTHREADS) {
        inp_s[r * 64 + (r & 31)] = x[(b0 + r) * TT + (TT - 1)];
    }
    // ---- c state lives in registers for the whole recurrence ----
    float c[4][4];
    #pragma unroll
    for (int rr = 0; rr < 4; rr++)
        #pragma unroll
        for (int jj = 0; jj < 4; jj++)
            c[rr][jj] = c0[(b0 + row0 + rr) * HH + (j0 + jj)];

    for (int t = 0; t < PP; t++) {
        // ---- stream this step's z features into inp_s cols 1..63 ----
        for (int idx = tid; idx < MROWS * FF; idx += NTHREADS) {
            int r = idx / FF;
            int f = idx - r * FF;
            inp_s[r * 64 + ((1 + f) ^ (r & 31))] =
                z[((b0 + r) * TT + (TT - PP + t)) * FF + f];
        }
        __syncthreads();

        // ---- gates GEMM: acc[row][type][j] over k = 0..191 ----
        float acc[4][4][4];
        #pragma unroll
        for (int rr = 0; rr < 4; rr++)
            #pragma unroll
            for (int ty = 0; ty < 4; ty++)
                #pragma unroll
                for (int jj = 0; jj < 4; jj++)
                    acc[rr][ty][jj] = 0.0f;

        // input part (k in [0,64): col 0 = prev out, cols 1..63 = z)
        #pragma unroll 4
        for (int k = 0; k < II; k++) {
            const float* wr = &g_Wt[k * GG];
            float4 wv[4];
            #pragma unroll
            for (int ty = 0; ty < 4; ty++)
                wv[ty] = *(const float4*)&wr[ty * 128 + j0];
            float v[4];
            #pragma unroll
            for (int rr = 0; rr < 4; rr++) {
                int row = row0 + rr;
                v[rr] = inp_s[row * 64 + (k ^ (row & 31))];
            }
            #pragma unroll
            for (int rr = 0; rr < 4; rr++)
                #pragma unroll
                for (int ty = 0; ty < 4; ty++) {
                    acc[rr][ty][0] += v[rr] * wv[ty].x;
                    acc[rr][ty][1] += v[rr] * wv[ty].y;
                    acc[rr][ty][2] += v[rr] * wv[ty].z;
                    acc[rr][ty][3] += v[rr] * wv[ty].w;
                }
        }
        // hidden part (k in [0,128))
        #pragma unroll 4
        for (int k = 0; k < HH; k++) {
            const float* wr = &g_Wt[(II + k) * GG];
            float4 wv[4];
            #pragma unroll
            for (int ty = 0; ty < 4; ty++)
                wv[ty] = *(const float4*)&wr[ty * 128 + j0];
            float v[4];
            #pragma unroll
            for (int rr = 0; rr < 4; rr++) {
                int row = row0 + rr;
                v[rr] = h_s[row * 128 + (k ^ (row & 31))];
            }
            #pragma unroll
            for (int rr = 0; rr < 4; rr++)
                #pragma unroll
                for (int ty = 0; ty < 4; ty++) {
                    acc[rr][ty][0] += v[rr] * wv[ty].x;
                    acc[rr][ty][1] += v[rr] * wv[ty].y;
                    acc[rr][ty][2] += v[rr] * wv[ty].z;
                    acc[rr][ty][3] += v[rr] * wv[ty].w;
                }
        }
        __syncthreads();   // everyone done reading h_s / inp_s

        // ---- pointwise LSTM cell update; write new h into h_s ----
        #pragma unroll
        for (int rr = 0; rr < 4; rr++) {
            int row = row0 + rr;
            #pragma unroll
            for (int jj = 0; jj < 4; jj++) {
                int j = j0 + jj;
                float gi = acc[rr][0][jj] + __ldg(&g_bsum[0 * 128 + j]);
                float gf = acc[rr][1][jj] + __ldg(&g_bsum[1 * 128 + j]);
                float gg = acc[rr][2][jj] + __ldg(&g_bsum[2 * 128 + j]);
                float go = acc[rr][3][jj] + __ldg(&g_bsum[3 * 128 + j]);
                float cn = sigf(gf) * c[rr][jj] + sigf(gi) * tanhf(gg);
                c[rr][jj] = cn;
                float hv = sigf(go) * tanhf(cn);
                h_s[row * 128 + (j ^ (row & 31))] = hv;
            }
        }
        __syncthreads();   // h_s complete

        // ---- out = h @ W_out.T + b_out : one thread per batch row ----
        if (tid < MROWS) {
            int r = tid;
            float s = 0.0f;
            #pragma unroll 8
            for (int k = 0; k < HH; k++)
                s += h_s[r * 128 + (k ^ (r & 31))] * __ldg(&Wout[k]);
            s += __ldg(&bout[0]);
            inp_s[r * 64 + (r & 31)] = s;            // recurrent input, next step
            Y[(b0 + r) * PP + t] = s;                // output (B, P, 1)
        }
        __syncthreads();
    }
}

extern "C" void kernel_launch(void* const* d_in, const int* in_sizes, int n_in,
                              void* d_out, int out_size) {
    const float* x    = (const float*)d_in[0];
    const float* z    = (const float*)d_in[1];
    const float* h0   = (const float*)d_in[2];
    const float* c0   = (const float*)d_in[3];
    const float* Wih  = (const float*)d_in[4];
    const float* Whh  = (const float*)d_in[5];
    const float* bih  = (const float*)d_in[6];
    const float* bhh  = (const float*)d_in[7];
    const float* Wout = (const float*)d_in[8];
    const float* bout = (const float*)d_in[9];
    float* Y = (float*)d_out;

    setup_kernel<<<192, 512>>>(Wih, Whh, bih, bhh);
    lstm_kernel<<<NBLOCKS, NTHREADS>>>(x, z, h0, c0, Wout, bout, Y);
}

// round 10
// speedup vs baseline: 6.4762x; 6.4762x over previous
#include <cuda_runtime.h>
#include <cstdint>

#define TT 128
#define FF 63
#define PP 64
#define NT 512

// Weight image: [ks 0..23][s 0..7][j 0..7][lane 0..31] -> float2 (b0: k=ks*8+(lane&3), b1: k+4)
// column n = s*64 + j*8 + (lane>>2), type-minor: col = 4*jl + type, gate g = type*128 + jl
__device__ float2 g_Wimg[24 * 8 * 8 * 32];
__device__ float  g_bias[512];

static __device__ __forceinline__ uint32_t cvt_tf32(float x) {
    uint32_t r; asm("cvt.rna.tf32.f32 %0, %1;" : "=r"(r) : "f"(x)); return r;
}
static __device__ __forceinline__ float th_(float x) {
    float r; asm("tanh.approx.f32 %0, %1;" : "=f"(r) : "f"(x)); return r;
}
static __device__ __forceinline__ float sg_(float x) { return fmaf(0.5f, th_(0.5f * x), 0.5f); }

static __device__ __forceinline__ int frag_off(int row, int k) {
    int mt = row >> 4, tr = row & 15, ks = k >> 3, kc = k & 7;
    int lane = ((tr & 7) << 2) | (kc & 3);
    int idx  = ((tr >> 3) & 1) | ((kc >> 2) << 1);
    return ((mt * 24 + ks) * 32 + lane) * 4 + idx;
}

static __device__ __forceinline__ void mma8(float* d, uint4 a, uint2 b) {
    asm volatile("mma.sync.aligned.m16n8k8.row.col.f32.tf32.tf32.f32 "
        "{%0,%1,%2,%3}, {%4,%5,%6,%7}, {%8,%9}, {%0,%1,%2,%3};"
        : "+f"(d[0]), "+f"(d[1]), "+f"(d[2]), "+f"(d[3])
        : "r"(a.x), "r"(a.y), "r"(a.z), "r"(a.w), "r"(b.x), "r"(b.y));
}

__global__ void setup_kernel(const float* __restrict__ Wih, const float* __restrict__ Whh,
                             const float* __restrict__ bih, const float* __restrict__ bhh,
                             const float* __restrict__ Wout, const float* __restrict__ bout) {
    int idx = blockIdx.x * blockDim.x + threadIdx.x;   // 0..49151
    if (idx < 49152) {
        int lane = idx & 31, j = (idx >> 5) & 7, s = (idx >> 8) & 7, ks = idx >> 11;
        int n = s * 64 + j * 8 + (lane >> 2);
        int g = (n & 3) * 128 + (n >> 2);              // type*128 + jl
        int k0 = ks * 8 + (lane & 3);
        float v0, v1;
        // folded weights: k<64 -> Wih; k>=64 -> Whh + Wih[:,0] (x) Wout
        v0 = (k0 < 64) ? Wih[g * 64 + k0]
                       : Whh[g * 128 + (k0 - 64)] + Wih[g * 64] * Wout[k0 - 64];
        int k1 = k0 + 4;
        v1 = (k1 < 64) ? Wih[g * 64 + k1]
                       : Whh[g * 128 + (k1 - 64)] + Wih[g * 64] * Wout[k1 - 64];
        float2 o;
        o.x = __uint_as_float(cvt_tf32(v0));
        o.y = __uint_as_float(cvt_tf32(v1));
        g_Wimg[idx] = o;
        if (idx < 512)
            g_bias[idx] = bih[idx] + bhh[idx] + Wih[idx * 64] * bout[0];
    }
}

// Dynamic SMEM layout (floats):
//   [0, 12288)       A fragments (tf32 bits), [mt 0..3][ks 0..23][lane][4]
//   [12288, 20736)   c-state, index row*132 + jl  (stride 132: bank-spread)
//   [20736, 21248)   bias[512]
//   [21248, 21376)   Wout[128]
//   [21376, 21440)   outacc[64]
#define SMF_TOTAL 21440

__global__ __launch_bounds__(NT, 1)
void lstm_mma(const float* __restrict__ x,  const float* __restrict__ z,
              const float* __restrict__ h0, const float* __restrict__ c0,
              const float* __restrict__ Wout, const float* __restrict__ bout,
              float* __restrict__ Y) {
    extern __shared__ float sm[];
    float* A_F   = sm;
    float* CSTf  = sm + 12288;
    float* BIASf = sm + 20736;
    float* WOUTf = sm + 21248;
    float* OACC  = sm + 21376;
    uint32_t* A_U = (uint32_t*)A_F;

    const int tid = threadIdx.x;
    const int w = tid >> 5, lane = tid & 31;
    const int s = w & 7, wm = w >> 3;         // n-stripe, m-stripe
    const int tpr = lane >> 2, c = lane & 3;
    const bool odd = (c & 1);
    const int b0 = blockIdx.x * 64;
    const float bout0 = __ldg(bout);

    // ---- one-time init ----
    for (int e = tid; e < 512; e += NT) BIASf[e] = g_bias[e];
    for (int e = tid; e < 128; e += NT) WOUTf[e] = __ldg(&Wout[e]);
    if (tid < 64) OACC[tid] = 0.0f;
    // h0 -> A frag (k = 64..191)
    for (int e = tid; e < 8192; e += NT) {
        int row = e >> 7, kk = e & 127;
        A_U[frag_off(row, 64 + kk)] = cvt_tf32(h0[(b0 + row) * 128 + kk]);
    }
    // z_0 -> A frag (k = 1..63)
    for (int e = tid; e < 64 * FF; e += NT) {
        int row = e / FF, f = e - row * FF;
        A_U[frag_off(row, 1 + f)] = cvt_tf32(z[((b0 + row) * TT + 64) * FF + f]);
    }
    // delta -> A col 0 (t=0 correction for folded out-recurrence)
    if (tid < 64) {
        int row = tid;
        float d = x[(b0 + row) * TT + (TT - 1)] - bout0;
        for (int jv = 0; jv < 128; ++jv)
            d -= h0[(b0 + row) * 128 + jv] * __ldg(&Wout[jv]);
        A_U[frag_off(row, 0)] = cvt_tf32(d);
    }
    // c0 -> SMEM c-state (per-cell ownership)
    #pragma unroll
    for (int m = 0; m < 2; ++m)
        #pragma unroll
        for (int jj = 0; jj < 4; ++jj) {
            int jl = s * 16 + 4 * jj + 2 * (c & 1) + (c >> 1);
            #pragma unroll
            for (int slot = 0; slot < 2; ++slot) {
                int row = wm * 32 + m * 16 + tpr + slot * 8;
                CSTf[row * 132 + jl] = c0[(b0 + row) * 128 + jl];
            }
        }
    __syncthreads();

    const uint2* wp = (const uint2*)g_Wimg;
    const int wbase = s * 256 + lane;
    const uint4* Au = (const uint4*)A_F;

    for (int t = 0; t < PP; ++t) {
        // ---- prefetch z_{t+1} (DRAM latency hidden under MMA) ----
        float zreg[8];
        {
            int zrow = tid >> 3;
            #pragma unroll
            for (int i = 0; i < 8; ++i) {
                int f = (tid & 7) * 8 + i;
                zreg[i] = (t < PP - 1 && f < FF)
                        ? z[((b0 + zrow) * TT + 64 + t + 1) * FF + f] : 0.0f;
            }
        }

        // ---- GEMM: D[64,512] = A[64,192] x W' (tf32 mma.sync) ----
        float acc[2][8][4];
        #pragma unroll
        for (int m = 0; m < 2; ++m)
            #pragma unroll
            for (int j = 0; j < 8; ++j)
                #pragma unroll
                for (int k2 = 0; k2 < 4; ++k2) acc[m][j][k2] = 0.0f;

        uint2 bc[8], bn[8];
        #pragma unroll
        for (int j = 0; j < 8; ++j) bc[j] = __ldg(&wp[wbase + j * 32]);

        #pragma unroll 4
        for (int ks = 0; ks < 24; ++ks) {
            if (ks < 23) {
                #pragma unroll
                for (int j = 0; j < 8; ++j)
                    bn[j] = __ldg(&wp[(ks + 1) * 2048 + wbase + j * 32]);
            }
            uint4 a0 = Au[((wm * 2 + 0) * 24 + ks) * 32 + lane];
            uint4 a1 = Au[((wm * 2 + 1) * 24 + ks) * 32 + lane];
            #pragma unroll
            for (int j = 0; j < 8; ++j) {
                mma8(acc[0][j], a0, bc[j]);
                mma8(acc[1][j], a1, bc[j]);
            }
            #pragma unroll
            for (int j = 0; j < 8; ++j) bc[j] = bn[j];
        }
        __syncthreads();   // all A reads done before epilogue overwrites A

        // ---- epilogue: pair exchange + cell update + h writeback ----
        float opart[2][2] = {{0.0f, 0.0f}, {0.0f, 0.0f}};
        #pragma unroll
        for (int m = 0; m < 2; ++m) {
            #pragma unroll
            for (int jj = 0; jj < 4; ++jj) {
                float re[4], ro[4];
                #pragma unroll
                for (int k2 = 0; k2 < 4; ++k2) {
                    re[k2] = __shfl_xor_sync(0xFFFFFFFFu, acc[m][2 * jj][k2], 1);
                    ro[k2] = __shfl_xor_sync(0xFFFFFFFFu, acc[m][2 * jj + 1][k2], 1);
                }
                const int jl = s * 16 + 4 * jj + 2 * (c & 1) + (c >> 1);
                const float bi = BIASf[jl],       bf = BIASf[128 + jl];
                const float bg = BIASf[256 + jl], bo = BIASf[384 + jl];
                const float wj = WOUTf[jl];
                #pragma unroll
                for (int slot = 0; slot < 2; ++slot) {
                    float mA = odd ? acc[m][2 * jj + 1][2 * slot]     : acc[m][2 * jj][2 * slot];
                    float mB = odd ? acc[m][2 * jj + 1][2 * slot + 1] : acc[m][2 * jj][2 * slot + 1];
                    float pA = odd ? ro[2 * slot]     : re[2 * slot];
                    float pB = odd ? ro[2 * slot + 1] : re[2 * slot + 1];
                    float gi_ = odd ? pA : mA;   // i
                    float gf_ = odd ? pB : mB;   // f
                    float gg_ = odd ? mA : pA;   // g
                    float go_ = odd ? mB : pB;   // o
                    int row = wm * 32 + m * 16 + tpr + slot * 8;
                    float i_ = sg_(gi_ + bi), f_ = sg_(gf_ + bf);
                    float g_ = th_(gg_ + bg), o_ = sg_(go_ + bo);
                    float cn = f_ * CSTf[row * 132 + jl] + i_ * g_;
                    CSTf[row * 132 + jl] = cn;
                    float h = o_ * th_(cn);
                    A_U[frag_off(row, 64 + jl)] = cvt_tf32(h);
                    opart[m][slot] += h * wj;
                }
            }
        }
        #pragma unroll
        for (int m = 0; m < 2; ++m)
            #pragma unroll
            for (int slot = 0; slot < 2; ++slot)
                atomicAdd(&OACC[wm * 32 + m * 16 + tpr + slot * 8], opart[m][slot]);

        // z_{t+1} scatter into A cols 1..63
        {
            int zrow = tid >> 3;
            #pragma unroll
            for (int i = 0; i < 8; ++i) {
                int f = (tid & 7) * 8 + i;
                if (f < FF) A_U[frag_off(zrow, 1 + f)] = cvt_tf32(zreg[i]);
            }
        }
        if (t == 0 && tid < 64) A_U[frag_off(tid, 0)] = 0u;   // delta column dies
        __syncthreads();   // h/z complete; outacc complete

        if (tid < 64) {
            Y[(b0 + tid) * PP + t] = OACC[tid] + bout0;
            OACC[tid] = 0.0f;   // safe: next atomics come after next barrier pair
        }
    }
}

extern "C" void kernel_launch(void* const* d_in, const int* in_sizes, int n_in,
                              void* d_out, int out_size) {
    const float* x    = (const float*)d_in[0];
    const float* z    = (const float*)d_in[1];
    const float* h0   = (const float*)d_in[2];
    const float* c0   = (const float*)d_in[3];
    const float* Wih  = (const float*)d_in[4];
    const float* Whh  = (const float*)d_in[5];
    const float* bih  = (const float*)d_in[6];
    const float* bhh  = (const float*)d_in[7];
    const float* Wout = (const float*)d_in[8];
    const float* bout = (const float*)d_in[9];
    float* Y = (float*)d_out;

    setup_kernel<<<96, 512>>>(Wih, Whh, bih, bhh, Wout, bout);
    cudaFuncSetAttribute(lstm_mma, cudaFuncAttributeMaxDynamicSharedMemorySize,
                         SMF_TOTAL * 4);
    lstm_mma<<<128, NT, SMF_TOTAL * 4>>>(x, z, h0, c0, Wout, bout, Y);
}

// round 11
// speedup vs baseline: 9.7548x; 1.5063x over previous
#include <cuda_runtime.h>
#include <cuda_fp16.h>
#include <cstdint>

#define TT 128
#define FF 63
#define PP 64
#define NT 512

// fp16 weight image: [ks 0..11][s 0..7][j 0..7][lane 0..31] -> uint2
//   reg0 halves: k = ks*16 + 2c, +1 ; reg1: k = ks*16 + 8 + 2c, +1 ; col = s*64+j*8+tpr
//   type-minor col n -> gate g = (n&3)*128 + (n>>2)
__device__ uint2 g_WimgH[12 * 8 * 8 * 32];
__device__ float g_bias[512];

static __device__ __forceinline__ float th_(float x) {
    float r; asm("tanh.approx.f32 %0, %1;" : "=f"(r) : "f"(x)); return r;
}
static __device__ __forceinline__ float sg_(float x) { return fmaf(0.5f, th_(0.5f * x), 0.5f); }

// half-element offset of (row, k) inside the A fragment image
static __device__ __forceinline__ int frag_off_h(int row, int k) {
    int mt = row >> 4, tr = row & 15, ks = k >> 4, kc = k & 15;
    int lane = ((tr & 7) << 2) | ((kc & 7) >> 1);
    int reg  = ((tr >> 3) & 1) | ((kc >> 3) << 1);
    return (((mt * 12 + ks) * 32 + lane) * 4 + reg) * 2 + (kc & 1);
}

static __device__ __forceinline__ void mma16(float* d, uint4 a, uint2 b) {
    asm volatile("mma.sync.aligned.m16n8k16.row.col.f32.f16.f16.f32 "
        "{%0,%1,%2,%3}, {%4,%5,%6,%7}, {%8,%9}, {%0,%1,%2,%3};"
        : "+f"(d[0]), "+f"(d[1]), "+f"(d[2]), "+f"(d[3])
        : "r"(a.x), "r"(a.y), "r"(a.z), "r"(a.w), "r"(b.x), "r"(b.y));
}

static __device__ __forceinline__ float wfold(const float* Wih, const float* Whh,
                                              const float* Wout, int g, int k) {
    return (k < 64) ? Wih[g * 64 + k]
                    : Whh[g * 128 + (k - 64)] + Wih[g * 64] * Wout[k - 64];
}

__global__ void setup_kernel(const float* __restrict__ Wih, const float* __restrict__ Whh,
                             const float* __restrict__ bih, const float* __restrict__ bhh,
                             const float* __restrict__ Wout, const float* __restrict__ bout) {
    int idx = blockIdx.x * blockDim.x + threadIdx.x;   // 0..24575
    if (idx < 24576) {
        int lane = idx & 31, j = (idx >> 5) & 7, s = (idx >> 8) & 7, ks = idx >> 11;
        int tpr = lane >> 2, c = lane & 3;
        int n = s * 64 + j * 8 + tpr;
        int g = (n & 3) * 128 + (n >> 2);
        int kb = ks * 16;
        __half2 lo = __floats2half2_rn(wfold(Wih, Whh, Wout, g, kb + 2 * c),
                                       wfold(Wih, Whh, Wout, g, kb + 2 * c + 1));
        __half2 hi = __floats2half2_rn(wfold(Wih, Whh, Wout, g, kb + 8 + 2 * c),
                                       wfold(Wih, Whh, Wout, g, kb + 8 + 2 * c + 1));
        uint2 o; o.x = *(uint32_t*)&lo; o.y = *(uint32_t*)&hi;
        g_WimgH[idx] = o;
        if (idx < 512)
            g_bias[idx] = bih[idx] + bhh[idx] + Wih[idx * 64] * bout[0];
    }
}

// Dynamic SMEM (bytes):
//   [0, 24576)        A fragments, fp16  [mt 0..3][ks 0..11][lane][4 regs][2 halves]
//   [24576, 58368)    c-state f32, row*132 + jl
//   [58368, 60416)    bias[512]
//   [60416, 60928)    Wout[128]
//   [60928, 61184)    outacc[64]
#define SMB_TOTAL 61184

__global__ __launch_bounds__(NT, 1)
void lstm_mma(const float* __restrict__ x,  const float* __restrict__ z,
              const float* __restrict__ h0, const float* __restrict__ c0,
              const float* __restrict__ Wout, const float* __restrict__ bout,
              float* __restrict__ Y) {
    extern __shared__ float sm[];
    __half* A_H   = (__half*)sm;
    float*  CSTf  = sm + 6144;
    float*  BIASf = sm + 14592;
    float*  WOUTf = sm + 15104;
    float*  OACC  = sm + 15232;
    const uint4* Au = (const uint4*)sm;

    const int tid = threadIdx.x;
    const int w = tid >> 5, lane = tid & 31;
    const int s = w & 7, wm = w >> 3;
    const int tpr = lane >> 2, c = lane & 3;
    const bool odd = (c & 1);
    const int b0 = blockIdx.x * 64;
    const float bout0 = __ldg(bout);

    // ---- one-time init ----
    for (int e = tid; e < 512; e += NT) BIASf[e] = g_bias[e];
    for (int e = tid; e < 128; e += NT) WOUTf[e] = __ldg(&Wout[e]);
    if (tid < 64) OACC[tid] = 0.0f;
    for (int e = tid; e < 8192; e += NT) {              // h0 -> A (k 64..191)
        int row = e >> 7, kk = e & 127;
        A_H[frag_off_h(row, 64 + kk)] = __float2half_rn(h0[(b0 + row) * 128 + kk]);
    }
    for (int e = tid; e < 64 * FF; e += NT) {           // z_0 -> A (k 1..63)
        int row = e / FF, f = e - row * FF;
        A_H[frag_off_h(row, 1 + f)] = __float2half_rn(z[((b0 + row) * TT + 64) * FF + f]);
    }
    if (tid < 64) {                                     // delta -> A col 0
        int row = tid;
        float d = x[(b0 + row) * TT + (TT - 1)] - bout0;
        for (int jv = 0; jv < 128; ++jv)
            d -= h0[(b0 + row) * 128 + jv] * __ldg(&Wout[jv]);
        A_H[frag_off_h(row, 0)] = __float2half_rn(d);
    }
    #pragma unroll
    for (int m = 0; m < 2; ++m)                         // c0 -> SMEM c-state
        #pragma unroll
        for (int jj = 0; jj < 4; ++jj) {
            int jl = s * 16 + 4 * jj + 2 * (c & 1) + (c >> 1);
            #pragma unroll
            for (int slot = 0; slot < 2; ++slot) {
                int row = wm * 32 + m * 16 + tpr + slot * 8;
                CSTf[row * 132 + jl] = c0[(b0 + row) * 128 + jl];
            }
        }
    __syncthreads();

    const uint2* wp = (const uint2*)g_WimgH;
    const int wbase = s * 256 + lane;

    for (int t = 0; t < PP; ++t) {
        // ---- prefetch z_{t+1} under the GEMM ----
        float zreg[8];
        {
            int zrow = tid >> 3;
            #pragma unroll
            for (int i = 0; i < 8; ++i) {
                int f = (tid & 7) * 8 + i;
                zreg[i] = (t < PP - 1 && f < FF)
                        ? z[((b0 + zrow) * TT + 64 + t + 1) * FF + f] : 0.0f;
            }
        }

        // ---- GEMM: D[64,512] = A[64,192] x W' (fp16 mma, f32 acc) ----
        float acc[2][8][4];
        #pragma unroll
        for (int m = 0; m < 2; ++m)
            #pragma unroll
            for (int j = 0; j < 8; ++j)
                #pragma unroll
                for (int k2 = 0; k2 < 4; ++k2) acc[m][j][k2] = 0.0f;

        uint2 bc[8], bn[8];
        #pragma unroll
        for (int j = 0; j < 8; ++j) bc[j] = __ldg(&wp[wbase + j * 32]);

        #pragma unroll
        for (int ks = 0; ks < 12; ++ks) {
            if (ks < 11) {
                #pragma unroll
                for (int j = 0; j < 8; ++j)
                    bn[j] = __ldg(&wp[(ks + 1) * 2048 + wbase + j * 32]);
            }
            uint4 a0 = Au[((wm * 2 + 0) * 12 + ks) * 32 + lane];
            uint4 a1 = Au[((wm * 2 + 1) * 12 + ks) * 32 + lane];
            #pragma unroll
            for (int j = 0; j < 8; ++j) {
                mma16(acc[0][j], a0, bc[j]);
                mma16(acc[1][j], a1, bc[j]);
            }
            #pragma unroll
            for (int j = 0; j < 8; ++j) bc[j] = bn[j];
        }
        __syncthreads();   // A reads complete before epilogue overwrites A

        // ---- epilogue: pair exchange + cell update + h writeback ----
        float opart[2][2] = {{0.0f, 0.0f}, {0.0f, 0.0f}};
        #pragma unroll
        for (int m = 0; m < 2; ++m) {
            #pragma unroll
            for (int jj = 0; jj < 4; ++jj) {
                float re[4], ro[4];
                #pragma unroll
                for (int k2 = 0; k2 < 4; ++k2) {
                    re[k2] = __shfl_xor_sync(0xFFFFFFFFu, acc[m][2 * jj][k2], 1);
                    ro[k2] = __shfl_xor_sync(0xFFFFFFFFu, acc[m][2 * jj + 1][k2], 1);
                }
                const int jl = s * 16 + 4 * jj + 2 * (c & 1) + (c >> 1);
                const float bi = BIASf[jl],       bf = BIASf[128 + jl];
                const float bg = BIASf[256 + jl], bo = BIASf[384 + jl];
                const float wj = WOUTf[jl];
                #pragma unroll
                for (int slot = 0; slot < 2; ++slot) {
                    float mA = odd ? acc[m][2 * jj + 1][2 * slot]     : acc[m][2 * jj][2 * slot];
                    float mB = odd ? acc[m][2 * jj + 1][2 * slot + 1] : acc[m][2 * jj][2 * slot + 1];
                    float pA = odd ? ro[2 * slot]     : re[2 * slot];
                    float pB = odd ? ro[2 * slot + 1] : re[2 * slot + 1];
                    float gi_ = odd ? pA : mA;
                    float gf_ = odd ? pB : mB;
                    float gg_ = odd ? mA : pA;
                    float go_ = odd ? mB : pB;
                    int row = wm * 32 + m * 16 + tpr + slot * 8;
                    float i_ = sg_(gi_ + bi), f_ = sg_(gf_ + bf);
                    float g_ = th_(gg_ + bg), o_ = sg_(go_ + bo);
                    float cn = f_ * CSTf[row * 132 + jl] + i_ * g_;
                    CSTf[row * 132 + jl] = cn;
                    float h = o_ * th_(cn);
                    A_H[frag_off_h(row, 64 + jl)] = __float2half_rn(h);
                    opart[m][slot] += h * wj;
                }
            }
        }
        #pragma unroll
        for (int m = 0; m < 2; ++m)
            #pragma unroll
            for (int slot = 0; slot < 2; ++slot)
                atomicAdd(&OACC[wm * 32 + m * 16 + tpr + slot * 8], opart[m][slot]);

        // z_{t+1} scatter into A cols 1..63
        {
            int zrow = tid >> 3;
            #pragma unroll
            for (int i = 0; i < 8; ++i) {
                int f = (tid & 7) * 8 + i;
                if (f < FF) A_H[frag_off_h(zrow, 1 + f)] = __float2half_rn(zreg[i]);
            }
        }
        if (t == 0 && tid < 64) A_H[frag_off_h(tid, 0)] = __float2half_rn(0.0f);
        __syncthreads();   // h/z/outacc complete

        if (tid < 64) {
            Y[(b0 + tid) * PP + t] = OACC[tid] + bout0;
            OACC[tid] = 0.0f;
        }
    }
}

extern "C" void kernel_launch(void* const* d_in, const int* in_sizes, int n_in,
                              void* d_out, int out_size) {
    const float* x    = (const float*)d_in[0];
    const float* z    = (const float*)d_in[1];
    const float* h0   = (const float*)d_in[2];
    const float* c0   = (const float*)d_in[3];
    const float* Wih  = (const float*)d_in[4];
    const float* Whh  = (const float*)d_in[5];
    const float* bih  = (const float*)d_in[6];
    const float* bhh  = (const float*)d_in[7];
    const float* Wout = (const float*)d_in[8];
    const float* bout = (const float*)d_in[9];
    float* Y = (float*)d_out;

    setup_kernel<<<48, 512>>>(Wih, Whh, bih, bhh, Wout, bout);
    cudaFuncSetAttribute(lstm_mma, cudaFuncAttributeMaxDynamicSharedMemorySize, SMB_TOTAL);
    lstm_mma<<<128, NT, SMB_TOTAL>>>(x, z, h0, c0, Wout, bout, Y);
}

// round 13
// speedup vs baseline: 13.4037x; 1.3741x over previous
#include <cuda_runtime.h>
#include <cuda_fp16.h>
#include <cstdint>

#define TT 128
#define FF 63
#define PP 64
#define NT 512

// fp16 weight image: [ks 0..11][s 0..7][j 0..7][lane 0..31] -> uint2
//   k: reg0 = ks*16 + 2c,+1 ; reg1 = +8  (c = lane&3)
//   col v = lane>>2 within frag; gate mapping (no-shuffle layout):
//   jl = s*16 + 4*(j&3) + (v>>1), type = (j>>2)*2 + (v&1), g = type*128 + jl
__device__ uint2 g_WimgH[12 * 8 * 8 * 32];
__device__ float g_bias[512];

static __device__ __forceinline__ float th_(float x) {
    float r; asm("tanh.approx.f32 %0, %1;" : "=f"(r) : "f"(x)); return r;
}
static __device__ __forceinline__ float sg_(float x) { return fmaf(0.5f, th_(0.5f * x), 0.5f); }

// half-element offset of (row, k) inside the A fragment image
static __device__ __forceinline__ int frag_off_h(int row, int k) {
    int mt = row >> 4, tr = row & 15, ks = k >> 4, kc = k & 15;
    int lane = ((tr & 7) << 2) | ((kc & 7) >> 1);
    int reg  = ((tr >> 3) & 1) | ((kc >> 3) << 1);
    return (((mt * 12 + ks) * 32 + lane) * 4 + reg) * 2 + (kc & 1);
}

static __device__ __forceinline__ void mma16(float* d, uint4 a, uint2 b) {
    asm volatile("mma.sync.aligned.m16n8k16.row.col.f32.f16.f16.f32 "
        "{%0,%1,%2,%3}, {%4,%5,%6,%7}, {%8,%9}, {%0,%1,%2,%3};"
        : "+f"(d[0]), "+f"(d[1]), "+f"(d[2]), "+f"(d[3])
        : "r"(a.x), "r"(a.y), "r"(a.z), "r"(a.w), "r"(b.x), "r"(b.y));
}

static __device__ __forceinline__ float wfold(const float* Wih, const float* Whh,
                                              const float* Wout, int g, int k) {
    return (k < 64) ? Wih[g * 64 + k]
                    : Whh[g * 128 + (k - 64)] + Wih[g * 64] * Wout[k - 64];
}

__global__ void setup_kernel(const float* __restrict__ Wih, const float* __restrict__ Whh,
                             const float* __restrict__ bih, const float* __restrict__ bhh,
                             const float* __restrict__ Wout, const float* __restrict__ bout) {
    int idx = blockIdx.x * blockDim.x + threadIdx.x;   // 0..24575
    if (idx < 24576) {
        int lane = idx & 31, j = (idx >> 5) & 7, s = (idx >> 8) & 7, ks = idx >> 11;
        int tpr = lane >> 2, c = lane & 3;
        int jl   = s * 16 + 4 * (j & 3) + (tpr >> 1);
        int type = (j >> 2) * 2 + (tpr & 1);
        int g = type * 128 + jl;
        int kb = ks * 16;
        __half2 lo = __floats2half2_rn(wfold(Wih, Whh, Wout, g, kb + 2 * c),
                                       wfold(Wih, Whh, Wout, g, kb + 2 * c + 1));
        __half2 hi = __floats2half2_rn(wfold(Wih, Whh, Wout, g, kb + 8 + 2 * c),
                                       wfold(Wih, Whh, Wout, g, kb + 8 + 2 * c + 1));
        uint2 o; o.x = *(uint32_t*)&lo; o.y = *(uint32_t*)&hi;
        g_WimgH[idx] = o;
        if (idx < 512)
            g_bias[idx] = bih[idx] + bhh[idx] + Wih[idx * 64] * bout[0];
    }
}

// Dynamic SMEM (floats):
//   [0, 6144)        A fragments fp16 (64 rows)
//   [6144, 14592)    c-state f32, row*132 + jl
//   [14592, 15104)   bias[512]
//   [15104, 15232)   Wout[128]
//   [15232, 17344)   OACC3: per half 32x33 (padded, conflict-free)
#define SMF_TOTAL 17344

__global__ __launch_bounds__(NT, 1)
void lstm_mma(const float* __restrict__ x,  const float* __restrict__ z,
              const float* __restrict__ h0, const float* __restrict__ c0,
              const float* __restrict__ Wout, const float* __restrict__ bout,
              float* __restrict__ Y) {
    extern __shared__ float sm[];
    __half* A_H   = (__half*)sm;
    float*  CSTf  = sm + 6144;
    float*  BIASf = sm + 14592;
    float*  WOUTf = sm + 15104;
    float*  OACC3 = sm + 15232;
    const uint4* Au = (const uint4*)sm;

    const int tid = threadIdx.x;
    const int half = tid >> 8, t256 = tid & 255;
    const int w8 = t256 >> 5, lane = tid & 31;
    const int s = w8;                          // n-stripe 0..7
    const int tpr = lane >> 2, c = lane & 3;
    const int b0 = blockIdx.x * 64;
    const float bout0 = __ldg(bout);

    // ---- one-time init (whole block) ----
    for (int e = tid; e < 512; e += NT) BIASf[e] = g_bias[e];
    for (int e = tid; e < 128; e += NT) WOUTf[e] = __ldg(&Wout[e]);
    for (int e = tid; e < 8192; e += NT) {              // h0 -> A (k 64..191)
        int row = e >> 7, kk = e & 127;
        A_H[frag_off_h(row, 64 + kk)] = __float2half_rn(h0[(b0 + row) * 128 + kk]);
    }
    for (int e = tid; e < 64 * FF; e += NT) {           // z_0 -> A (k 1..63)
        int row = e / FF, f = e - row * FF;
        A_H[frag_off_h(row, 1 + f)] = __float2half_rn(z[((b0 + row) * TT + 64) * FF + f]);
    }
    if (tid < 64) {                                     // delta -> A col 0
        int row = tid;
        float d = x[(b0 + row) * TT + (TT - 1)] - bout0;
        for (int jv = 0; jv < 128; ++jv)
            d -= h0[(b0 + row) * 128 + jv] * __ldg(&Wout[jv]);
        A_H[frag_off_h(row, 0)] = __float2half_rn(d);
    }
    for (int e = tid; e < 8192; e += NT) {              // c0 -> c-state
        int row = e >> 7, jl = e & 127;
        CSTf[row * 132 + jl] = c0[(b0 + row) * 128 + jl];
    }
    __syncthreads();

    const uint2* wp = (const uint2*)g_WimgH;
    const int wbase = s * 256 + lane;
    const int mt0 = half * 2, mt1 = half * 2 + 1;
    float* OACCh = OACC3 + half * 1056;

    uint2 bc[8], bn[8];
    #pragma unroll
    for (int j = 0; j < 8; ++j) bc[j] = __ldg(&wp[wbase + j * 32]);

    for (int t = 0; t < PP; ++t) {
        // ---- prefetch z_{t+1} under the GEMM ----
        float zreg[8];
        {
            int zrow = half * 32 + (t256 >> 3);
            #pragma unroll
            for (int i = 0; i < 8; ++i) {
                int f = (t256 & 7) * 8 + i;
                zreg[i] = (t < PP - 1 && f < FF)
                        ? z[((b0 + zrow) * TT + 64 + t + 1) * FF + f] : 0.0f;
            }
        }

        // ---- GEMM: D[32,512] per half ----
        float acc[2][8][4];
        #pragma unroll
        for (int m = 0; m < 2; ++m)
            #pragma unroll
            for (int j = 0; j < 8; ++j)
                #pragma unroll
                for (int k2 = 0; k2 < 4; ++k2) acc[m][j][k2] = 0.0f;

        #pragma unroll
        for (int ks = 0; ks < 12; ++ks) {
            int ksn = (ks == 11) ? 0 : ks + 1;      // rotate: tail loads next step's ks=0
            #pragma unroll
            for (int j = 0; j < 8; ++j)
                bn[j] = __ldg(&wp[ksn * 2048 + wbase + j * 32]);
            uint4 a0 = Au[(mt0 * 12 + ks) * 32 + lane];
            uint4 a1 = Au[(mt1 * 12 + ks) * 32 + lane];
            #pragma unroll
            for (int j = 0; j < 8; ++j) {
                mma16(acc[0][j], a0, bc[j]);
                mma16(acc[1][j], a1, bc[j]);
            }
            #pragma unroll
            for (int j = 0; j < 8; ++j) bc[j] = bn[j];
        }
        asm volatile("bar.sync %0, 256;" :: "r"(half + 1) : "memory");  // A reads done

        // ---- epilogue: all 4 gates in-thread (no shuffles) ----
        float opart[2][2] = {{0.0f, 0.0f}, {0.0f, 0.0f}};
        #pragma unroll
        for (int m = 0; m < 2; ++m) {
            #pragma unroll
            for (int j = 0; j < 4; ++j) {
                const int jl = s * 16 + 4 * j + c;
                const float bi = BIASf[jl],       bf = BIASf[128 + jl];
                const float bg = BIASf[256 + jl], bo = BIASf[384 + jl];
                const float wj = WOUTf[jl];
                #pragma unroll
                for (int slot = 0; slot < 2; ++slot) {
                    float gi_ = acc[m][j][2 * slot];
                    float gf_ = acc[m][j][2 * slot + 1];
                    float gg_ = acc[m][j + 4][2 * slot];
                    float go_ = acc[m][j + 4][2 * slot + 1];
                    int row = half * 32 + m * 16 + tpr + slot * 8;
                    float i_ = sg_(gi_ + bi), f_ = sg_(gf_ + bf);
                    float g_ = th_(gg_ + bg), o_ = sg_(go_ + bo);
                    float cn = f_ * CSTf[row * 132 + jl] + i_ * g_;
                    CSTf[row * 132 + jl] = cn;
                    float hv = o_ * th_(cn);
                    A_H[frag_off_h(row, 64 + jl)] = __float2half_rn(hv);
                    opart[m][slot] += hv * wj;
                }
            }
        }
        #pragma unroll
        for (int m = 0; m < 2; ++m)
            #pragma unroll
            for (int slot = 0; slot < 2; ++slot) {
                int rl = m * 16 + tpr + slot * 8;          // 0..31 within half
                OACCh[rl * 33 + s * 4 + c] = opart[m][slot];
            }

        // z_{t+1} scatter into A cols 1..63
        {
            int zrow = half * 32 + (t256 >> 3);
            #pragma unroll
            for (int i = 0; i < 8; ++i) {
                int f = (t256 & 7) * 8 + i;
                if (f < FF) A_H[frag_off_h(zrow, 1 + f)] = __float2half_rn(zreg[i]);
            }
        }
        if (t == 0 && t256 < 32)
            A_H[frag_off_h(half * 32 + t256, 0)] = __float2half_rn(0.0f);
        asm volatile("bar.sync %0, 256;" :: "r"(half + 1) : "memory");  // writes done

        if (t256 < 32) {    // Y: sum 32 stripe-partials (overlaps next MMA of others)
            const float* p = &OACCh[t256 * 33];
            float ssum = 0.0f;
            #pragma unroll
            for (int u = 0; u < 32; ++u) ssum += p[u];
            Y[(b0 + half * 32 + t256) * PP + t] = ssum + bout0;
        }
    }
}

extern "C" void kernel_launch(void* const* d_in, const int* in_sizes, int n_in,
                              void* d_out, int out_size) {
    const float* x    = (const float*)d_in[0];
    const float* z    = (const float*)d_in[1];
    const float* h0   = (const float*)d_in[2];
    const float* c0   = (const float*)d_in[3];
    const float* Wih  = (const float*)d_in[4];
    const float* Whh  = (const float*)d_in[5];
    const float* bih  = (const float*)d_in[6];
    const float* bhh  = (const float*)d_in[7];
    const float* Wout = (const float*)d_in[8];
    const float* bout = (const float*)d_in[9];
    float* Y = (float*)d_out;

    setup_kernel<<<48, 512>>>(Wih, Whh, bih, bhh, Wout, bout);
    cudaFuncSetAttribute(lstm_mma, cudaFuncAttributeMaxDynamicSharedMemorySize,
                         SMF_TOTAL * 4);
    lstm_mma<<<128, NT, SMF_TOTAL * 4>>>(x, z, h0, c0, Wout, bout, Y);
}